// round 15
// baseline (speedup 1.0000x reference)
#include <cuda_runtime.h>
#include <cuda_fp16.h>
#include <math.h>

#define NQ 4096
#define NKEY 4096
#define FD 256
#define NH 8
#define HD 32
#define SCALE 0.17677669529663689f   // 1/sqrt(32)
#define SCL2E 0.25503487f            // SCALE * log2(e)
#define R2 9.0f                      // LOCAL_RADIUS^2
#define MAX_NBR 1024

#define TM 128       // GEMM tile rows
#define TN 64        // GEMM tile cols
#define KC 64        // k-chunk
#define KCP 72       // padded smem row stride in halves (144B rows, LDSM conflict-free)

// smem layout (in halves), double-buffered
#define SZ_A   (TM * KCP)            // 9216
#define SZ_W   (TN * KCP)            // 4608
#define OFF_AH 0
#define OFF_AL (2 * SZ_A)            // 18432
#define OFF_WH (4 * SZ_A)            // 36864
#define OFF_WL (OFF_WH + 2 * SZ_W)   // 46080
#define SMEM_HALVES (OFF_WL + 2 * SZ_W)          // 55296
#define SMEM_BYTES  (SMEM_HALVES * 2)            // 110592

// Scratch (device-global: no allocations allowed)
__device__ float  g_Q[NQ * FD];
__device__ __half g_KV[NKEY * 2 * FD];   // row k: [K row | V row], 1KB stride
__device__ int    g_nbr[NQ * MAX_NBR];
__device__ int    g_cnt[NQ];

// Pre-split (hi, lo) fp16 operands
__device__ __half g_cfh[NQ * FD],   g_cfl[NQ * FD];
__device__ __half g_hfh[NKEY * FD], g_hfl[NKEY * FD];
__device__ __half g_Ah[NQ * FD],    g_Al[NQ * FD];
__device__ __half g_Wqh[FD * FD], g_Wql[FD * FD];
__device__ __half g_Wkh[FD * FD], g_Wkl[FD * FD];
__device__ __half g_Wvh[FD * FD], g_Wvl[FD * FD];
__device__ __half g_Woh[FD * FD], g_Wol[FD * FD];

// ---------------------------------------------------------------------------
// Split: x = h + l exactly to ~22 bits (h = fp16(x), l = fp16(x - h)).
// ---------------------------------------------------------------------------
__device__ __forceinline__ void split4(float4 v, __half2& h0, __half2& h1,
                                       __half2& l0, __half2& l1)
{
    __half hx = __float2half_rn(v.x), hy = __float2half_rn(v.y);
    __half hz = __float2half_rn(v.z), hw = __float2half_rn(v.w);
    h0 = __halves2half2(hx, hy);
    h1 = __halves2half2(hz, hw);
    l0 = __floats2half2_rn(v.x - __half2float(hx), v.y - __half2float(hy));
    l1 = __floats2half2_rn(v.z - __half2float(hz), v.w - __half2float(hw));
}

// Splits cf, hf and the 4 weight matrices in one launch (blockIdx.y selects).
__global__ __launch_bounds__(256) void split6_kernel(
    const float* __restrict__ cf, const float* __restrict__ hf,
    const float* __restrict__ Wq, const float* __restrict__ Wk,
    const float* __restrict__ Wv, const float* __restrict__ Wo,
    __half* __restrict__ cfh, __half* __restrict__ cfl,
    __half* __restrict__ hfh, __half* __restrict__ hfl,
    __half* __restrict__ Wqh, __half* __restrict__ Wql,
    __half* __restrict__ Wkh, __half* __restrict__ Wkl,
    __half* __restrict__ Wvh, __half* __restrict__ Wvl,
    __half* __restrict__ Woh, __half* __restrict__ Wol)
{
    const float* src; __half *dh, *dl; int n4;
    switch (blockIdx.y) {
        case 0: src = cf; dh = cfh; dl = cfl; n4 = NQ * FD / 4; break;
        case 1: src = hf; dh = hfh; dl = hfl; n4 = NKEY * FD / 4; break;
        case 2: src = Wq; dh = Wqh; dl = Wql; n4 = FD * FD / 4; break;
        case 3: src = Wk; dh = Wkh; dl = Wkl; n4 = FD * FD / 4; break;
        case 4: src = Wv; dh = Wvh; dl = Wvl; n4 = FD * FD / 4; break;
        default: src = Wo; dh = Woh; dl = Wol; n4 = FD * FD / 4; break;
    }
    const int i = blockIdx.x * 256 + threadIdx.x;
    if (i >= n4) return;
    float4 v = ((const float4*)src)[i];
    __half2 h0, h1, l0, l1;
    split4(v, h0, h1, l0, l1);
    ((__half2*)dh)[i * 2] = h0; ((__half2*)dh)[i * 2 + 1] = h1;
    ((__half2*)dl)[i * 2] = l0; ((__half2*)dl)[i * 2 + 1] = l1;
}

// ---------------------------------------------------------------------------
// MMA / cp.async helpers
// ---------------------------------------------------------------------------
__device__ __forceinline__ void mma16816(float c[4],
                                         unsigned a0, unsigned a1, unsigned a2, unsigned a3,
                                         unsigned b0, unsigned b1)
{
    asm volatile(
        "mma.sync.aligned.m16n8k16.row.col.f32.f16.f16.f32 "
        "{%0,%1,%2,%3}, {%4,%5,%6,%7}, {%8,%9}, {%0,%1,%2,%3};\n"
        : "+f"(c[0]), "+f"(c[1]), "+f"(c[2]), "+f"(c[3])
        : "r"(a0), "r"(a1), "r"(a2), "r"(a3), "r"(b0), "r"(b1));
}

__device__ __forceinline__ void ldsm_x4(unsigned& r0, unsigned& r1,
                                        unsigned& r2, unsigned& r3, unsigned addr)
{
    asm volatile("ldmatrix.sync.aligned.m8n8.x4.shared.b16 {%0,%1,%2,%3}, [%4];\n"
                 : "=r"(r0), "=r"(r1), "=r"(r2), "=r"(r3) : "r"(addr));
}

#define CP16(saddr, gptr) \
    asm volatile("cp.async.ca.shared.global [%0], [%1], 16;\n" \
                 :: "r"(saddr), "l"(gptr))
#define CP_COMMIT() asm volatile("cp.async.commit_group;\n")
#define CP_WAIT0()  asm volatile("cp.async.wait_group 0;\n")

// ---------------------------------------------------------------------------
// Tensor-core GEMM on pre-split operands, 128x64 tile, 256 threads,
// double-buffered cp.async, single __syncthreads per k-chunk.
// 3-term split (hh+hl+lh) = fp32-exact. Warp w: rows [16w,16w+16) x 64 cols.
// hstr = row stride (elements) for the half output (supports interleaved KV).
// ---------------------------------------------------------------------------
__device__ __forceinline__ void tgemm_core(
    const __half* __restrict__ Agh, const __half* __restrict__ Agl,
    const __half* __restrict__ Wgh, const __half* __restrict__ Wgl,
    const float* __restrict__ bias,
    float* __restrict__ outF, __half* __restrict__ outH, int hstr,
    int row0, int col0)
{
    extern __shared__ __half sm[];
    const int tid  = threadIdx.x;
    const int lane = tid & 31;
    const int w    = tid >> 5;
    const int g    = lane >> 2;
    const int t4   = lane & 3;

    unsigned sb;
    asm volatile("{ .reg .u64 t; cvta.to.shared.u64 t, %1; cvt.u32.u64 %0, t; }"
                 : "=r"(sb) : "l"(&sm[0]));

    float acc[8][4];
#pragma unroll
    for (int n8 = 0; n8 < 8; n8++)
#pragma unroll
        for (int i = 0; i < 4; i++) acc[n8][i] = 0.f;

    const unsigned frow = lane & 15;
    const unsigned fk   = (lane >> 4) * 8;
    const unsigned aoff = ((w * 16 + frow) * KCP + fk) * 2;   // A lane offset (bytes)
    const unsigned woff = (frow * KCP + fk) * 2;              // W lane offset (bytes)

#define STAGE_CHUNK(BUF, KC0)                                                   \
    do {                                                                        \
        const int b_ = (BUF);                                                   \
        const int k0_ = (KC0);                                                  \
        _Pragma("unroll")                                                       \
        for (int it = 0; it < 4; it++) {                                        \
            const int s   = tid + it * 256;                                     \
            const int row = s >> 3;                                             \
            const int cg  = (s & 7) * 8;                                        \
            CP16(sb + (OFF_AH + b_ * SZ_A + row * KCP + cg) * 2,                \
                 &Agh[(row0 + row) * FD + k0_ + cg]);                           \
            CP16(sb + (OFF_AL + b_ * SZ_A + row * KCP + cg) * 2,                \
                 &Agl[(row0 + row) * FD + k0_ + cg]);                           \
        }                                                                       \
        _Pragma("unroll")                                                       \
        for (int it = 0; it < 2; it++) {                                        \
            const int s   = tid + it * 256;                                     \
            const int row = s >> 3;                                             \
            const int cg  = (s & 7) * 8;                                        \
            CP16(sb + (OFF_WH + b_ * SZ_W + row * KCP + cg) * 2,                \
                 &Wgh[(col0 + row) * FD + k0_ + cg]);                           \
            CP16(sb + (OFF_WL + b_ * SZ_W + row * KCP + cg) * 2,                \
                 &Wgl[(col0 + row) * FD + k0_ + cg]);                           \
        }                                                                       \
    } while (0)

    STAGE_CHUNK(0, 0);
    CP_COMMIT();

    const int NCHUNK = FD / KC;   // 4
#pragma unroll
    for (int c = 0; c < NCHUNK; c++) {
        CP_WAIT0();
        __syncthreads();
        if (c < NCHUNK - 1) {
            STAGE_CHUNK((c + 1) & 1, (c + 1) * KC);
            CP_COMMIT();
        }

        const int b = c & 1;
        const unsigned bAh = sb + (OFF_AH + b * SZ_A) * 2 + aoff;
        const unsigned bAl = sb + (OFF_AL + b * SZ_A) * 2 + aoff;
        const unsigned bWh = sb + (OFF_WH + b * SZ_W) * 2 + woff;
        const unsigned bWl = sb + (OFF_WL + b * SZ_W) * 2 + woff;

#pragma unroll
        for (int ks = 0; ks < KC / 16; ks++) {
            const unsigned kb2 = ks * 32;          // 16 halves = 32 bytes
            unsigned ah0, ah1, ah2, ah3, al0, al1, al2, al3;
            ldsm_x4(ah0, ah1, ah2, ah3, bAh + kb2);
            ldsm_x4(al0, al1, al2, al3, bAl + kb2);
#pragma unroll
            for (int ng = 0; ng < 4; ng++) {
                const unsigned wo = (unsigned)(ng * 16 * KCP * 2) + kb2;
                unsigned b0a, b0b, b1a, b1b, c0a, c0b, c1a, c1b;
                ldsm_x4(b0a, b0b, b1a, b1b, bWh + wo);
                ldsm_x4(c0a, c0b, c1a, c1b, bWl + wo);
                mma16816(acc[2 * ng],     ah0, ah1, ah2, ah3, b0a, b1a);
                mma16816(acc[2 * ng],     ah0, ah1, ah2, ah3, c0a, c1a);
                mma16816(acc[2 * ng],     al0, al1, al2, al3, b0a, b1a);
                mma16816(acc[2 * ng + 1], ah0, ah1, ah2, ah3, b0b, b1b);
                mma16816(acc[2 * ng + 1], ah0, ah1, ah2, ah3, c0b, c1b);
                mma16816(acc[2 * ng + 1], al0, al1, al2, al3, b0b, b1b);
            }
        }
    }
#undef STAGE_CHUNK

    // Epilogue: c0,c1 -> (row g, cols t4*2,+1); c2,c3 -> row g+8.
    const int rA = row0 + w * 16 + g;
#pragma unroll
    for (int n8 = 0; n8 < 8; n8++) {
        const int c = col0 + n8 * 8 + t4 * 2;
        const float b0 = bias[c], b1 = bias[c + 1];
        if (outF) {
            float2 o0; o0.x = acc[n8][0] + b0; o0.y = acc[n8][1] + b1;
            float2 o1; o1.x = acc[n8][2] + b0; o1.y = acc[n8][3] + b1;
            *(float2*)&outF[rA * FD + c]       = o0;
            *(float2*)&outF[(rA + 8) * FD + c] = o1;
        } else {
            *(__half2*)&outH[rA * hstr + c]       = __floats2half2_rn(acc[n8][0] + b0, acc[n8][1] + b1);
            *(__half2*)&outH[(rA + 8) * hstr + c] = __floats2half2_rn(acc[n8][2] + b0, acc[n8][3] + b1);
        }
    }
}

// Fused Q/K/V projection: blockIdx.z selects which GEMM.
// K writes rows at stride 2*FD (g_KV[k][0]); V at stride 2*FD offset FD.
__global__ __launch_bounds__(256) void qkv_gemm_kernel(
    const __half* __restrict__ cfh, const __half* __restrict__ cfl,
    const __half* __restrict__ hfh, const __half* __restrict__ hfl,
    const __half* __restrict__ Wqh, const __half* __restrict__ Wql, const float* __restrict__ bq,
    const __half* __restrict__ Wkh, const __half* __restrict__ Wkl, const float* __restrict__ bk,
    const __half* __restrict__ Wvh, const __half* __restrict__ Wvl, const float* __restrict__ bv,
    float* __restrict__ Qout, __half* __restrict__ KVout)
{
    const int row0 = blockIdx.y * TM;
    const int col0 = blockIdx.x * TN;
    if (blockIdx.z == 0)
        tgemm_core(cfh, cfl, Wqh, Wql, bq, Qout, nullptr, FD, row0, col0);
    else if (blockIdx.z == 1)
        tgemm_core(hfh, hfl, Wkh, Wkl, bk, nullptr, KVout, 2 * FD, row0, col0);
    else
        tgemm_core(hfh, hfl, Wvh, Wvl, bv, nullptr, KVout + FD, 2 * FD, row0, col0);
}

// Output projection (fp32 out).
__global__ __launch_bounds__(256) void wo_gemm_kernel(
    const __half* __restrict__ Ahh, const __half* __restrict__ All,
    const __half* __restrict__ Woh, const __half* __restrict__ Wol,
    const float* __restrict__ bo, float* __restrict__ C)
{
    tgemm_core(Ahh, All, Woh, Wol, bo, C, nullptr, FD, blockIdx.y * TM, blockIdx.x * TN);
}

// ---------------------------------------------------------------------------
// Neighbor list build v2: each warp scans for 4 queries serially, so the
// 48KB coord staging is amortized 4x (128 blocks instead of 512).
// ---------------------------------------------------------------------------
__global__ __launch_bounds__(256) void nbr_kernel(
    const float* __restrict__ qc, const float* __restrict__ kc,
    int* __restrict__ nbr, int* __restrict__ cnt)
{
    __shared__ float sx[NKEY], sy[NKEY], sz[NKEY];
    for (int i = threadIdx.x; i < NKEY; i += 256) {
        sx[i] = kc[i * 3 + 0];
        sy[i] = kc[i * 3 + 1];
        sz[i] = kc[i * 3 + 2];
    }
    __syncthreads();

    const int warp = threadIdx.x >> 5;
    const int lane = threadIdx.x & 31;
    const unsigned ltmask = (1u << lane) - 1u;

    for (int qi = 0; qi < 4; qi++) {
        const int q = blockIdx.x * 32 + warp * 4 + qi;

        const float qx = qc[q * 3 + 0];
        const float qy = qc[q * 3 + 1];
        const float qz = qc[q * 3 + 2];

        int c = 0;
        int* out = nbr + q * MAX_NBR;

        for (int i = lane; i < NKEY; i += 32) {
            const float dx = qx - sx[i];
            const float dy = qy - sy[i];
            const float dz = qz - sz[i];
            const bool act = fmaf(dx, dx, fmaf(dy, dy, dz * dz)) <= R2;
            const unsigned b = __ballot_sync(0xffffffffu, act);
            if (act) {
                const int pos = c + __popc(b & ltmask);
                if (pos < MAX_NBR) out[pos] = i;
            }
            c += __popc(b);
        }
        if (lane == 0) cnt[q] = (c < MAX_NBR) ? c : MAX_NBR;
    }
}

// ---------------------------------------------------------------------------
// Sparse attention v6: block = one query, 4 warps.
// Lane covers 16 dims (2 lanes per head); each HALF-WARP processes a whole
// neighbor, so the warp retires 2 neighbors/iteration with ONE shfl (xor 1)
// in the score chain. slot = lane>>4 selects which neighbor of the pair;
// cnt is block-uniform so loop control is warp-uniform; slot-1 tail is
// predicated (clamped index, e = 0). Tail merge: xor-16 shfl-adds, once.
// K and V rows interleaved (1KB stride): V address = K address + 512B.
// No max-shift (scores ~ N(0,1)).
// Epilogue writes the (hi, lo) fp16 split directly (feeds the Wo GEMM).
// ---------------------------------------------------------------------------
__global__ __launch_bounds__(128) void sattn_kernel(
    const float* __restrict__ Q, const __half* __restrict__ KV,
    const int* __restrict__ nbr, const int* __restrict__ cntp,
    __half* __restrict__ OAh, __half* __restrict__ OAl)
{
    __shared__ int   snb[MAX_NBR];
    __shared__ float s_acc[4][FD];
    __shared__ float s_sum[4][NH];

    const int q    = blockIdx.x;
    const int tid  = threadIdx.x;
    const int w    = tid >> 5;
    const int lane = tid & 31;
    const int cnt  = cntp[q];

    for (int i = tid; i < cnt; i += 128)
        snb[i] = nbr[q * MAX_NBR + i];
    __syncthreads();

    const int h2   = lane & 15;          // position within half-warp
    const int slot = lane >> 4;          // which neighbor of the pair
    const int head = h2 >> 1;
    const int d0   = head * HD + (h2 & 1) * 16;   // 16 dims per lane
    const __half* __restrict__ KVd = KV + d0;

    __half2 qh[8];
    {
#pragma unroll
        for (int i = 0; i < 4; i++) {
            float4 qv = *(const float4*)&Q[q * FD + d0 + i * 4];
            qh[2 * i]     = __floats2half2_rn(qv.x, qv.y);
            qh[2 * i + 1] = __floats2half2_rn(qv.z, qv.w);
        }
    }

    float accv[16];
#pragma unroll
    for (int i = 0; i < 16; i++) accv[i] = 0.f;
    float ssum = 0.f;

#pragma unroll 2
    for (int jb = w * 2; jb < cnt; jb += 8) {
        const int j     = jb + slot;
        const bool valid = j < cnt;
        const int jj    = valid ? j : cnt - 1;    // safe clamp (cnt >= 1 here)
        const __half* p = KVd + snb[jj] * (2 * FD);

        const uint4 kr0 = *(const uint4*)p;
        const uint4 kr1 = *(const uint4*)(p + 8);
        const uint4 vr0 = *(const uint4*)(p + FD);
        const uint4 vr1 = *(const uint4*)(p + FD + 8);

        // dot over this lane's 16 dims (8 HFMA2)
        __half2 ph = __hmul2(qh[0], *(const __half2*)&kr0.x);
        ph = __hfma2(qh[1], *(const __half2*)&kr0.y, ph);
        ph = __hfma2(qh[2], *(const __half2*)&kr0.z, ph);
        ph = __hfma2(qh[3], *(const __half2*)&kr0.w, ph);
        ph = __hfma2(qh[4], *(const __half2*)&kr1.x, ph);
        ph = __hfma2(qh[5], *(const __half2*)&kr1.y, ph);
        ph = __hfma2(qh[6], *(const __half2*)&kr1.z, ph);
        ph = __hfma2(qh[7], *(const __half2*)&kr1.w, ph);
        float pd = __low2float(ph) + __high2float(ph);
        pd += __shfl_xor_sync(0xffffffffu, pd, 1);     // head dot over 2 lanes

        const float e = valid ? exp2f(pd * SCL2E) : 0.f;
        ssum += e;

        float2 t;
        t = __half22float2(*(const __half2*)&vr0.x);
        accv[0]  = fmaf(e, t.x, accv[0]);  accv[1]  = fmaf(e, t.y, accv[1]);
        t = __half22float2(*(const __half2*)&vr0.y);
        accv[2]  = fmaf(e, t.x, accv[2]);  accv[3]  = fmaf(e, t.y, accv[3]);
        t = __half22float2(*(const __half2*)&vr0.z);
        accv[4]  = fmaf(e, t.x, accv[4]);  accv[5]  = fmaf(e, t.y, accv[5]);
        t = __half22float2(*(const __half2*)&vr0.w);
        accv[6]  = fmaf(e, t.x, accv[6]);  accv[7]  = fmaf(e, t.y, accv[7]);
        t = __half22float2(*(const __half2*)&vr1.x);
        accv[8]  = fmaf(e, t.x, accv[8]);  accv[9]  = fmaf(e, t.y, accv[9]);
        t = __half22float2(*(const __half2*)&vr1.y);
        accv[10] = fmaf(e, t.x, accv[10]); accv[11] = fmaf(e, t.y, accv[11]);
        t = __half22float2(*(const __half2*)&vr1.z);
        accv[12] = fmaf(e, t.x, accv[12]); accv[13] = fmaf(e, t.y, accv[13]);
        t = __half22float2(*(const __half2*)&vr1.w);
        accv[14] = fmaf(e, t.x, accv[14]); accv[15] = fmaf(e, t.y, accv[15]);
    }

    // Merge the two half-warps (lanes l and l+16 cover the same dims).
#pragma unroll
    for (int i = 0; i < 16; i++)
        accv[i] += __shfl_xor_sync(0xffffffffu, accv[i], 16);
    ssum += __shfl_xor_sync(0xffffffffu, ssum, 16);

    // Publish partials (slot 0 half only).
    if (slot == 0) {
#pragma unroll
        for (int i = 0; i < 16; i += 4)
            *(float4*)&s_acc[w][d0 + i] =
                make_float4(accv[i], accv[i + 1], accv[i + 2], accv[i + 3]);
        if ((h2 & 1) == 0) s_sum[w][head] = ssum;
    }
    __syncthreads();

    // Combine: each thread finalizes 2 dims; write (hi, lo) fp16 split.
    const int d = tid * 2;
    const int hh = d >> 5;
    const float tot = s_sum[0][hh] + s_sum[1][hh] + s_sum[2][hh] + s_sum[3][hh];
    const float inv = (tot > 0.f) ? (1.0f / tot) : 0.f;
    const float a0 = (s_acc[0][d]     + s_acc[1][d]     + s_acc[2][d]     + s_acc[3][d])     * inv;
    const float a1 = (s_acc[0][d + 1] + s_acc[1][d + 1] + s_acc[2][d + 1] + s_acc[3][d + 1]) * inv;

    const __half h0 = __float2half_rn(a0);
    const __half h1 = __float2half_rn(a1);
    *(__half2*)&OAh[q * FD + d] = __halves2half2(h0, h1);
    *(__half2*)&OAl[q * FD + d] = __floats2half2_rn(a0 - __half2float(h0),
                                                    a1 - __half2float(h1));
}

// ---------------------------------------------------------------------------
extern "C" void kernel_launch(void* const* d_in, const int* in_sizes, int n_in,
                              void* d_out, int out_size)
{
    const float* cf = (const float*)d_in[0];
    const float* hf = (const float*)d_in[1];
    const float* cc = (const float*)d_in[2];
    const float* hc = (const float*)d_in[3];
    const float* Wq = (const float*)d_in[4];
    const float* bq = (const float*)d_in[5];
    const float* Wk = (const float*)d_in[6];
    const float* bk = (const float*)d_in[7];
    const float* Wv = (const float*)d_in[8];
    const float* bv = (const float*)d_in[9];
    const float* Wo = (const float*)d_in[10];
    const float* bo = (const float*)d_in[11];
    float* out = (float*)d_out;

    float *Qp;
    __half *KVp;
    int *nbrp, *cntp;
    __half *cfh, *cfl, *hfh, *hfl, *Ahp, *Alp;
    __half *Wqh, *Wql, *Wkh, *Wkl, *Wvh, *Wvl, *Woh, *Wol;
    cudaGetSymbolAddress((void**)&Qp, g_Q);
    cudaGetSymbolAddress((void**)&KVp, g_KV);
    cudaGetSymbolAddress((void**)&nbrp, g_nbr);
    cudaGetSymbolAddress((void**)&cntp, g_cnt);
    cudaGetSymbolAddress((void**)&cfh, g_cfh); cudaGetSymbolAddress((void**)&cfl, g_cfl);
    cudaGetSymbolAddress((void**)&hfh, g_hfh); cudaGetSymbolAddress((void**)&hfl, g_hfl);
    cudaGetSymbolAddress((void**)&Ahp, g_Ah);  cudaGetSymbolAddress((void**)&Alp, g_Al);
    cudaGetSymbolAddress((void**)&Wqh, g_Wqh); cudaGetSymbolAddress((void**)&Wql, g_Wql);
    cudaGetSymbolAddress((void**)&Wkh, g_Wkh); cudaGetSymbolAddress((void**)&Wkl, g_Wkl);
    cudaGetSymbolAddress((void**)&Wvh, g_Wvh); cudaGetSymbolAddress((void**)&Wvl, g_Wvl);
    cudaGetSymbolAddress((void**)&Woh, g_Woh); cudaGetSymbolAddress((void**)&Wol, g_Wol);

    cudaFuncSetAttribute(qkv_gemm_kernel,
                         cudaFuncAttributeMaxDynamicSharedMemorySize, SMEM_BYTES);
    cudaFuncSetAttribute(wo_gemm_kernel,
                         cudaFuncAttributeMaxDynamicSharedMemorySize, SMEM_BYTES);

    nbr_kernel<<<NQ / 32, 256>>>(cc, hc, nbrp, cntp);

    dim3 gs(NQ * FD / 4 / 256, 6);
    split6_kernel<<<gs, 256>>>(cf, hf, Wq, Wk, Wv, Wo,
                               cfh, cfl, hfh, hfl,
                               Wqh, Wql, Wkh, Wkl, Wvh, Wvl, Woh, Wol);

    dim3 gqkv(FD / TN, NQ / TM, 3);   // (4, 32, 3) = 384 blocks
    qkv_gemm_kernel<<<gqkv, 256, SMEM_BYTES>>>(cfh, cfl, hfh, hfl,
                                               Wqh, Wql, bq, Wkh, Wkl, bk, Wvh, Wvl, bv,
                                               Qp, KVp);

    sattn_kernel<<<NQ, 128>>>(Qp, KVp, nbrp, cntp, Ahp, Alp);

    dim3 gg(FD / TN, NQ / TM);        // (4, 32)
    wo_gemm_kernel<<<gg, 256, SMEM_BYTES>>>(Ahp, Alp, Woh, Wol, bo, out);
}